// round 1
// baseline (speedup 1.0000x reference)
#include <cuda_runtime.h>
#include <math.h>

#define T_TOK 8192
#define H_DIM 2048
#define I_DIM 2048
#define E_NUM 8
#define CAP   1280

// ---- scratch (static __device__ — no allocations) ----
__device__ int   g_top1[T_TOK];
__device__ float g_prob[T_TOK];
__device__ int   g_slot_tok[E_NUM * CAP];                      // token idx per (expert, slot), -1 = empty
__device__ float g_mid[(size_t)E_NUM * CAP * I_DIM];           // 80 MB intermediate

__device__ __forceinline__ float gelu_exact(float v) {
    return 0.5f * v * (1.0f + erff(v * 0.70710678118654752440f));
}

// ============================================================================
// 1) Gate: logits = x @ gw^T ; top-1 argmax + softmax prob of the argmax.
//    1 block = 16 tokens; 8 warps, warp w computes expert w's dot product.
// ============================================================================
__global__ void gate_kernel(const float* __restrict__ x, const float* __restrict__ gw) {
    __shared__ float st[H_DIM];
    __shared__ float slog[E_NUM];
    int tid = threadIdx.x;
    int warp = tid >> 5, lane = tid & 31;
    int t0 = blockIdx.x * 16;
    for (int tk = 0; tk < 16; tk++) {
        int t = t0 + tk;
        const float4* src = (const float4*)(x + (size_t)t * H_DIM);
        float4* dst = (float4*)st;
        for (int i = tid; i < H_DIM / 4; i += 256) dst[i] = src[i];
        __syncthreads();
        float s = 0.f;
        const float* g = gw + (size_t)warp * H_DIM;
        for (int i = lane; i < H_DIM; i += 32) s += st[i] * g[i];
        #pragma unroll
        for (int o = 16; o; o >>= 1) s += __shfl_xor_sync(0xffffffffu, s, o);
        if (lane == 0) slog[warp] = s;
        __syncthreads();
        if (tid == 0) {
            float mx = slog[0]; int am = 0;
            #pragma unroll
            for (int e = 1; e < E_NUM; e++) if (slog[e] > mx) { mx = slog[e]; am = e; }
            float den = 0.f;
            #pragma unroll
            for (int e = 0; e < E_NUM; e++) den += expf(slog[e] - mx);
            g_top1[t] = am;
            g_prob[t] = 1.0f / den;
        }
        __syncthreads();
    }
}

// ============================================================================
// 2) Routing scan: per-expert cumulative rank in token order, capacity drop.
//    Single block; 256 threads x 32 contiguous tokens; Hillis-Steele scan of
//    8-wide count vectors.
// ============================================================================
__global__ void scan_kernel() {
    __shared__ int sc[2][256][E_NUM];
    int tid = threadIdx.x;
    for (int i = tid; i < E_NUM * CAP; i += 256) g_slot_tok[i] = -1;
    int h[E_NUM];
    #pragma unroll
    for (int e = 0; e < E_NUM; e++) h[e] = 0;
    int base = tid * 32;
    for (int j = 0; j < 32; j++) h[g_top1[base + j]]++;
    #pragma unroll
    for (int e = 0; e < E_NUM; e++) sc[0][tid][e] = h[e];
    __syncthreads();
    int src = 0;
    for (int d = 1; d < 256; d <<= 1) {
        #pragma unroll
        for (int e = 0; e < E_NUM; e++) {
            int v = sc[src][tid][e];
            if (tid >= d) v += sc[src][tid - d][e];
            sc[1 - src][tid][e] = v;
        }
        __syncthreads();
        src ^= 1;
    }
    int run[E_NUM];
    #pragma unroll
    for (int e = 0; e < E_NUM; e++) run[e] = sc[src][tid][e] - h[e];  // exclusive prefix
    for (int j = 0; j < 32; j++) {
        int t = base + j;
        int e = g_top1[t];
        int r = run[e]++;
        if (r < CAP) g_slot_tok[e * CAP + r] = t;
    }
}

// ============================================================================
// 3) GEMM1: mid[e,c,:] = gelu( gather(x)[e,c,:] @ w1[e] )
//    128x128 block tile, K-step 16, 8x8 per thread, 256 threads.
//    A rows gathered via g_slot_tok (zero rows for empty slots).
// ============================================================================
__global__ __launch_bounds__(256, 2) void gemm1_kernel(
    const float* __restrict__ x, const float* __restrict__ w1) {
    int e  = blockIdx.z;
    int m0 = blockIdx.y * 128;
    int n0 = blockIdx.x * 128;
    if (g_slot_tok[e * CAP + m0] < 0) return;   // tile entirely beyond capacity-fill

    __shared__ float As[16][128];
    __shared__ float Bs[16][128];
    int tid = threadIdx.x;
    int ar = tid & 63;
    int ak = (tid >> 6) << 2;           // 0,4,8,12
    int tok0 = g_slot_tok[e * CAP + m0 + ar];
    int tok1 = g_slot_tok[e * CAP + m0 + ar + 64];
    const float* a0p = x + (size_t)(tok0 < 0 ? 0 : tok0) * H_DIM + ak;
    const float* a1p = x + (size_t)(tok1 < 0 ? 0 : tok1) * H_DIM + ak;
    int bk = tid >> 5;                  // 0..7
    int bn = (tid & 31) << 2;           // 0..124
    const float* bp = w1 + (size_t)e * H_DIM * I_DIM + (size_t)bk * I_DIM + n0 + bn;
    int tx = tid & 15, ty = tid >> 4;

    float acc[8][8];
    #pragma unroll
    for (int i = 0; i < 8; i++)
        #pragma unroll
        for (int j = 0; j < 8; j++) acc[i][j] = 0.f;

    for (int kt = 0; kt < H_DIM; kt += 16) {
        float4 a0 = (tok0 >= 0) ? *(const float4*)(a0p + kt) : make_float4(0.f, 0.f, 0.f, 0.f);
        float4 a1 = (tok1 >= 0) ? *(const float4*)(a1p + kt) : make_float4(0.f, 0.f, 0.f, 0.f);
        float4 b0 = *(const float4*)(bp + (size_t)kt * I_DIM);
        float4 b1 = *(const float4*)(bp + (size_t)(kt + 8) * I_DIM);
        As[ak + 0][ar] = a0.x; As[ak + 1][ar] = a0.y; As[ak + 2][ar] = a0.z; As[ak + 3][ar] = a0.w;
        As[ak + 0][ar + 64] = a1.x; As[ak + 1][ar + 64] = a1.y; As[ak + 2][ar + 64] = a1.z; As[ak + 3][ar + 64] = a1.w;
        *(float4*)&Bs[bk][bn] = b0;
        *(float4*)&Bs[bk + 8][bn] = b1;
        __syncthreads();
        #pragma unroll
        for (int kk = 0; kk < 16; kk++) {
            float4 aA = *(const float4*)&As[kk][ty * 8];
            float4 aB = *(const float4*)&As[kk][ty * 8 + 4];
            float4 bA = *(const float4*)&Bs[kk][tx * 8];
            float4 bB = *(const float4*)&Bs[kk][tx * 8 + 4];
            float av[8] = {aA.x, aA.y, aA.z, aA.w, aB.x, aB.y, aB.z, aB.w};
            float bv[8] = {bA.x, bA.y, bA.z, bA.w, bB.x, bB.y, bB.z, bB.w};
            #pragma unroll
            for (int i = 0; i < 8; i++)
                #pragma unroll
                for (int j = 0; j < 8; j++) acc[i][j] += av[i] * bv[j];
        }
        __syncthreads();
    }

    float* mp = g_mid + (size_t)e * CAP * I_DIM;
    #pragma unroll
    for (int i = 0; i < 8; i++) {
        int row = m0 + ty * 8 + i;
        float4 v0, v1;
        v0.x = gelu_exact(acc[i][0]); v0.y = gelu_exact(acc[i][1]);
        v0.z = gelu_exact(acc[i][2]); v0.w = gelu_exact(acc[i][3]);
        v1.x = gelu_exact(acc[i][4]); v1.y = gelu_exact(acc[i][5]);
        v1.z = gelu_exact(acc[i][6]); v1.w = gelu_exact(acc[i][7]);
        float* o = mp + (size_t)row * I_DIM + n0 + tx * 8;
        *(float4*)o = v0;
        *(float4*)(o + 4) = v1;
    }
}

// ============================================================================
// 4) GEMM2: out[tok,:] = prob[tok] * ( mid[e,c,:] @ w2[e] ), scatter by slot.
// ============================================================================
__global__ __launch_bounds__(256, 2) void gemm2_kernel(
    const float* __restrict__ w2, float* __restrict__ out) {
    int e  = blockIdx.z;
    int m0 = blockIdx.y * 128;
    int n0 = blockIdx.x * 128;
    if (g_slot_tok[e * CAP + m0] < 0) return;

    __shared__ float As[16][128];
    __shared__ float Bs[16][128];
    int tid = threadIdx.x;
    int ar = tid & 63;
    int ak = (tid >> 6) << 2;
    const float* a0p = g_mid + (size_t)e * CAP * I_DIM + (size_t)(m0 + ar) * I_DIM + ak;
    const float* a1p = a0p + (size_t)64 * I_DIM;
    int bk = tid >> 5;
    int bn = (tid & 31) << 2;
    const float* bp = w2 + (size_t)e * I_DIM * H_DIM + (size_t)bk * H_DIM + n0 + bn;
    int tx = tid & 15, ty = tid >> 4;

    float acc[8][8];
    #pragma unroll
    for (int i = 0; i < 8; i++)
        #pragma unroll
        for (int j = 0; j < 8; j++) acc[i][j] = 0.f;

    for (int kt = 0; kt < I_DIM; kt += 16) {
        float4 a0 = *(const float4*)(a0p + kt);
        float4 a1 = *(const float4*)(a1p + kt);
        float4 b0 = *(const float4*)(bp + (size_t)kt * H_DIM);
        float4 b1 = *(const float4*)(bp + (size_t)(kt + 8) * H_DIM);
        As[ak + 0][ar] = a0.x; As[ak + 1][ar] = a0.y; As[ak + 2][ar] = a0.z; As[ak + 3][ar] = a0.w;
        As[ak + 0][ar + 64] = a1.x; As[ak + 1][ar + 64] = a1.y; As[ak + 2][ar + 64] = a1.z; As[ak + 3][ar + 64] = a1.w;
        *(float4*)&Bs[bk][bn] = b0;
        *(float4*)&Bs[bk + 8][bn] = b1;
        __syncthreads();
        #pragma unroll
        for (int kk = 0; kk < 16; kk++) {
            float4 aA = *(const float4*)&As[kk][ty * 8];
            float4 aB = *(const float4*)&As[kk][ty * 8 + 4];
            float4 bA = *(const float4*)&Bs[kk][tx * 8];
            float4 bB = *(const float4*)&Bs[kk][tx * 8 + 4];
            float av[8] = {aA.x, aA.y, aA.z, aA.w, aB.x, aB.y, aB.z, aB.w};
            float bv[8] = {bA.x, bA.y, bA.z, bA.w, bB.x, bB.y, bB.z, bB.w};
            #pragma unroll
            for (int i = 0; i < 8; i++)
                #pragma unroll
                for (int j = 0; j < 8; j++) acc[i][j] += av[i] * bv[j];
        }
        __syncthreads();
    }

    #pragma unroll
    for (int i = 0; i < 8; i++) {
        int row = m0 + ty * 8 + i;
        int tok = g_slot_tok[e * CAP + row];
        if (tok < 0) continue;
        float p = g_prob[tok];
        float4 v0, v1;
        v0.x = p * acc[i][0]; v0.y = p * acc[i][1]; v0.z = p * acc[i][2]; v0.w = p * acc[i][3];
        v1.x = p * acc[i][4]; v1.y = p * acc[i][5]; v1.z = p * acc[i][6]; v1.w = p * acc[i][7];
        float* o = out + (size_t)tok * H_DIM + n0 + tx * 8;
        *(float4*)o = v0;
        *(float4*)(o + 4) = v1;
    }
}

// ============================================================================
extern "C" void kernel_launch(void* const* d_in, const int* in_sizes, int n_in,
                              void* d_out, int out_size) {
    const float* x  = (const float*)d_in[0];   // [2,4096,2048]
    const float* gw = (const float*)d_in[1];   // [8,2048]
    const float* w1 = (const float*)d_in[2];   // [8,2048,2048]
    const float* w2 = (const float*)d_in[3];   // [8,2048,2048]
    float* out = (float*)d_out;

    gate_kernel<<<T_TOK / 16, 256>>>(x, gw);
    scan_kernel<<<1, 256>>>();
    cudaMemsetAsync(d_out, 0, (size_t)out_size * sizeof(float));
    gemm1_kernel<<<dim3(I_DIM / 128, CAP / 128, E_NUM), 256>>>(x, w1);
    gemm2_kernel<<<dim3(H_DIM / 128, CAP / 128, E_NUM), 256>>>(w2, out);
}

// round 14
// speedup vs baseline: 3.1638x; 3.1638x over previous
#include <cuda_runtime.h>
#include <math.h>
#include <stdint.h>

#define T_TOK 8192
#define H_DIM 2048
#define I_DIM 2048
#define E_NUM 8
#define CAP   1280

#define NCHUNK 64              // K=2048 / 32
#define AST 36                 // A smem row stride (floats)
#define BST 136                // B smem row stride (floats)
#define A_ELEMS (128 * AST)    // 4608
#define B_ELEMS (32 * BST)     // 4352
#define STAGE_ELEMS (A_ELEMS + B_ELEMS)
#define SMEM_BYTES (2 * STAGE_ELEMS * 4)

// ---- scratch (static __device__ — no allocations) ----
__device__ int   g_top1[T_TOK];
__device__ float g_prob[T_TOK];
__device__ int   g_slot_tok[E_NUM * CAP];
__device__ float g_mid[(size_t)E_NUM * CAP * I_DIM];

// ---------------------------------------------------------------- helpers ---
__device__ __forceinline__ uint32_t smem_u32(const void* p) {
    uint32_t a;
    asm("{ .reg .u64 t; cvta.to.shared.u64 t, %1; cvt.u32.u64 %0, t; }" : "=r"(a) : "l"(p));
    return a;
}
__device__ __forceinline__ uint32_t f2tf32(float f) {
    uint32_t u;
    asm("cvt.rna.tf32.f32 %0, %1;" : "=r"(u) : "f"(f));
    return u;
}
__device__ __forceinline__ float gelu_exact(float v) {
    return 0.5f * v * (1.0f + erff(v * 0.70710678118654752440f));
}
__device__ __forceinline__ void mma_tf32(float* c, const uint32_t* a, uint32_t b0, uint32_t b1) {
    asm volatile(
        "mma.sync.aligned.m16n8k8.row.col.f32.tf32.tf32.f32 "
        "{%0,%1,%2,%3}, {%4,%5,%6,%7}, {%8,%9}, {%0,%1,%2,%3};"
        : "+f"(c[0]), "+f"(c[1]), "+f"(c[2]), "+f"(c[3])
        : "r"(a[0]), "r"(a[1]), "r"(a[2]), "r"(a[3]), "r"(b0), "r"(b1));
}
#define CP16(dst, src, sz) \
    asm volatile("cp.async.cg.shared.global [%0], [%1], 16, %2;" \
                 :: "r"(dst), "l"(src), "r"(sz) : "memory")
#define CP_COMMIT() asm volatile("cp.async.commit_group;" ::: "memory")
#define CP_WAIT0()  asm volatile("cp.async.wait_group 0;" ::: "memory")

// ============================================================================
// 1) Gate
// ============================================================================
__global__ void gate_kernel(const float* __restrict__ x, const float* __restrict__ gw) {
    __shared__ float st[H_DIM];
    __shared__ float slog[E_NUM];
    int tid = threadIdx.x;
    int warp = tid >> 5, lane = tid & 31;
    int t0 = blockIdx.x * 16;
    for (int tk = 0; tk < 16; tk++) {
        int t = t0 + tk;
        const float4* src = (const float4*)(x + (size_t)t * H_DIM);
        float4* dst = (float4*)st;
        for (int i = tid; i < H_DIM / 4; i += 256) dst[i] = src[i];
        __syncthreads();
        float s = 0.f;
        const float* g = gw + (size_t)warp * H_DIM;
        for (int i = lane; i < H_DIM; i += 32) s += st[i] * g[i];
        #pragma unroll
        for (int o = 16; o; o >>= 1) s += __shfl_xor_sync(0xffffffffu, s, o);
        if (lane == 0) slog[warp] = s;
        __syncthreads();
        if (tid == 0) {
            float mx = slog[0]; int am = 0;
            #pragma unroll
            for (int e = 1; e < E_NUM; e++) if (slog[e] > mx) { mx = slog[e]; am = e; }
            float den = 0.f;
            #pragma unroll
            for (int e = 0; e < E_NUM; e++) den += expf(slog[e] - mx);
            g_top1[t] = am;
            g_prob[t] = 1.0f / den;
        }
        __syncthreads();
    }
}

// ============================================================================
// 2) Routing scan
// ============================================================================
__global__ void scan_kernel() {
    __shared__ int sc[2][256][E_NUM];
    int tid = threadIdx.x;
    for (int i = tid; i < E_NUM * CAP; i += 256) g_slot_tok[i] = -1;
    int h[E_NUM];
    #pragma unroll
    for (int e = 0; e < E_NUM; e++) h[e] = 0;
    int base = tid * 32;
    for (int j = 0; j < 32; j++) h[g_top1[base + j]]++;
    #pragma unroll
    for (int e = 0; e < E_NUM; e++) sc[0][tid][e] = h[e];
    __syncthreads();
    int src = 0;
    for (int d = 1; d < 256; d <<= 1) {
        #pragma unroll
        for (int e = 0; e < E_NUM; e++) {
            int v = sc[src][tid][e];
            if (tid >= d) v += sc[src][tid - d][e];
            sc[1 - src][tid][e] = v;
        }
        __syncthreads();
        src ^= 1;
    }
    int run[E_NUM];
    #pragma unroll
    for (int e = 0; e < E_NUM; e++) run[e] = sc[src][tid][e] - h[e];
    for (int j = 0; j < 32; j++) {
        int t = base + j;
        int e = g_top1[t];
        int r = run[e]++;
        if (r < CAP) g_slot_tok[e * CAP + r] = t;
    }
}

// ============================================================================
// 3) GEMM1 (mma.sync tf32): mid = gelu( gather(x) @ w1[e] )
//    128x128x32 tile, 8 warps (warp 32x64), cp.async double buffer.
// ============================================================================
__global__ __launch_bounds__(256, 2) void gemm1_mma(
    const float* __restrict__ x, const float* __restrict__ w1) {
    int e = blockIdx.z, m0 = blockIdx.x * 128, n0 = blockIdx.y * 128;
    if (g_slot_tok[e * CAP + m0] < 0) return;
    extern __shared__ float smem[];
    uint32_t sb = smem_u32(smem);
    int tid = threadIdx.x, lane = tid & 31, wid = tid >> 5;
    int gid = lane >> 2, tig = lane & 3;
    int wm = wid & 3, wn = wid >> 2;

    // A: 4 cp.async/thread/chunk (gathered rows, zero-fill for empty slots)
    const float* agp[4]; uint32_t aso[4], asz[4];
    #pragma unroll
    for (int i = 0; i < 4; i++) {
        int idx = tid + i * 256, row = idx >> 3, seg = idx & 7;
        int tok = g_slot_tok[e * CAP + m0 + row];
        asz[i] = (tok >= 0) ? 16u : 0u;
        agp[i] = x + (size_t)(tok < 0 ? 0 : tok) * H_DIM + seg * 4;
        aso[i] = (uint32_t)(row * AST + seg * 4) * 4u;
    }
    // B: 4 cp.async/thread/chunk (full 32x128 tile = 1024 segments)
    const float* bgp[4]; uint32_t bso[4];
    const float* wbase = w1 + (size_t)e * H_DIM * I_DIM;
    #pragma unroll
    for (int i = 0; i < 4; i++) {
        int idx = tid + i * 256, brow = idx >> 5, bseg = idx & 31;
        bgp[i] = wbase + (size_t)brow * I_DIM + n0 + bseg * 4;
        bso[i] = (uint32_t)(A_ELEMS + brow * BST + bseg * 4) * 4u;
    }

    float c[2][8][4];
    #pragma unroll
    for (int mf = 0; mf < 2; mf++)
        #pragma unroll
        for (int j = 0; j < 8; j++)
            #pragma unroll
            for (int q = 0; q < 4; q++) c[mf][j][q] = 0.f;

    // preload chunk 0
    {
        uint32_t base = sb;
        #pragma unroll
        for (int i = 0; i < 4; i++) CP16(base + aso[i], agp[i], asz[i]);
        #pragma unroll
        for (int i = 0; i < 4; i++) CP16(base + bso[i], bgp[i], 16u);
        CP_COMMIT();
    }

    for (int kc = 0; kc < NCHUNK; kc++) {
        int buf = kc & 1;
        CP_WAIT0();
        __syncthreads();
        if (kc + 1 < NCHUNK) {
            uint32_t base = sb + (uint32_t)((buf ^ 1) * STAGE_ELEMS * 4);
            int kt = (kc + 1) * 32;
            #pragma unroll
            for (int i = 0; i < 4; i++) CP16(base + aso[i], agp[i] + kt, asz[i]);
            #pragma unroll
            for (int i = 0; i < 4; i++) CP16(base + bso[i], bgp[i] + (size_t)kt * I_DIM, 16u);
            CP_COMMIT();
        }
        const float* As = smem + buf * STAGE_ELEMS;
        const float* Bs = As + A_ELEMS;
        #pragma unroll
        for (int k8 = 0; k8 < 4; k8++) {
            int kk = k8 * 8;
            uint32_t a[2][4];
            #pragma unroll
            for (int mf = 0; mf < 2; mf++) {
                int r0 = wm * 32 + mf * 16 + gid;
                a[mf][0] = f2tf32(As[r0 * AST + kk + tig]);
                a[mf][1] = f2tf32(As[(r0 + 8) * AST + kk + tig]);
                a[mf][2] = f2tf32(As[r0 * AST + kk + tig + 4]);
                a[mf][3] = f2tf32(As[(r0 + 8) * AST + kk + tig + 4]);
            }
            #pragma unroll
            for (int j = 0; j < 8; j++) {
                int nn = wn * 64 + j * 8 + gid;
                uint32_t b0 = f2tf32(Bs[(kk + tig) * BST + nn]);
                uint32_t b1 = f2tf32(Bs[(kk + tig + 4) * BST + nn]);
                mma_tf32(c[0][j], a[0], b0, b1);
                mma_tf32(c[1][j], a[1], b0, b1);
            }
        }
        __syncthreads();
    }

    // epilogue: gelu -> g_mid
    #pragma unroll
    for (int mf = 0; mf < 2; mf++) {
        int row = m0 + wm * 32 + mf * 16 + gid;
        #pragma unroll
        for (int j = 0; j < 8; j++) {
            int col = n0 + wn * 64 + j * 8 + tig * 2;
            float* p0 = g_mid + ((size_t)e * CAP + row) * I_DIM + col;
            float2 v0 = make_float2(gelu_exact(c[mf][j][0]), gelu_exact(c[mf][j][1]));
            float2 v1 = make_float2(gelu_exact(c[mf][j][2]), gelu_exact(c[mf][j][3]));
            *(float2*)p0 = v0;
            *(float2*)(p0 + (size_t)8 * I_DIM) = v1;
        }
    }
}

// ============================================================================
// 4) GEMM2 (mma.sync tf32): out[tok] = prob[tok] * ( mid @ w2[e] ), scatter
// ============================================================================
__global__ __launch_bounds__(256, 2) void gemm2_mma(
    const float* __restrict__ w2, float* __restrict__ out) {
    int e = blockIdx.z, m0 = blockIdx.x * 128, n0 = blockIdx.y * 128;
    if (g_slot_tok[e * CAP + m0] < 0) return;
    extern __shared__ float smem[];
    uint32_t sb = smem_u32(smem);
    int tid = threadIdx.x, lane = tid & 31, wid = tid >> 5;
    int gid = lane >> 2, tig = lane & 3;
    int wm = wid & 3, wn = wid >> 2;

    const float* agp[4]; uint32_t aso[4];
    #pragma unroll
    for (int i = 0; i < 4; i++) {
        int idx = tid + i * 256, row = idx >> 3, seg = idx & 7;
        agp[i] = g_mid + ((size_t)e * CAP + m0 + row) * I_DIM + seg * 4;
        aso[i] = (uint32_t)(row * AST + seg * 4) * 4u;
    }
    const float* bgp[4]; uint32_t bso[4];
    const float* wbase = w2 + (size_t)e * I_DIM * H_DIM;
    #pragma unroll
    for (int i = 0; i < 4; i++) {
        int idx = tid + i * 256, brow = idx >> 5, bseg = idx & 31;
        bgp[i] = wbase + (size_t)brow * H_DIM + n0 + bseg * 4;
        bso[i] = (uint32_t)(A_ELEMS + brow * BST + bseg * 4) * 4u;
    }

    float c[2][8][4];
    #pragma unroll
    for (int mf = 0; mf < 2; mf++)
        #pragma unroll
        for (int j = 0; j < 8; j++)
            #pragma unroll
            for (int q = 0; q < 4; q++) c[mf][j][q] = 0.f;

    {
        uint32_t base = sb;
        #pragma unroll
        for (int i = 0; i < 4; i++) CP16(base + aso[i], agp[i], 16u);
        #pragma unroll
        for (int i = 0; i < 4; i++) CP16(base + bso[i], bgp[i], 16u);
        CP_COMMIT();
    }

    for (int kc = 0; kc < NCHUNK; kc++) {
        int buf = kc & 1;
        CP_WAIT0();
        __syncthreads();
        if (kc + 1 < NCHUNK) {
            uint32_t base = sb + (uint32_t)((buf ^ 1) * STAGE_ELEMS * 4);
            int kt = (kc + 1) * 32;
            #pragma unroll
            for (int i = 0; i < 4; i++) CP16(base + aso[i], agp[i] + kt, 16u);
            #pragma unroll
            for (int i = 0; i < 4; i++) CP16(base + bso[i], bgp[i] + (size_t)kt * H_DIM, 16u);
            CP_COMMIT();
        }
        const float* As = smem + buf * STAGE_ELEMS;
        const float* Bs = As + A_ELEMS;
        #pragma unroll
        for (int k8 = 0; k8 < 4; k8++) {
            int kk = k8 * 8;
            uint32_t a[2][4];
            #pragma unroll
            for (int mf = 0; mf < 2; mf++) {
                int r0 = wm * 32 + mf * 16 + gid;
                a[mf][0] = f2tf32(As[r0 * AST + kk + tig]);
                a[mf][1] = f2tf32(As[(r0 + 8) * AST + kk + tig]);
                a[mf][2] = f2tf32(As[r0 * AST + kk + tig + 4]);
                a[mf][3] = f2tf32(As[(r0 + 8) * AST + kk + tig + 4]);
            }
            #pragma unroll
            for (int j = 0; j < 8; j++) {
                int nn = wn * 64 + j * 8 + gid;
                uint32_t b0 = f2tf32(Bs[(kk + tig) * BST + nn]);
                uint32_t b1 = f2tf32(Bs[(kk + tig + 4) * BST + nn]);
                mma_tf32(c[0][j], a[0], b0, b1);
                mma_tf32(c[1][j], a[1], b0, b1);
            }
        }
        __syncthreads();
    }

    // epilogue: scale by prob, scatter to out (skip dropped slots)
    #pragma unroll
    for (int mf = 0; mf < 2; mf++) {
        int r0 = m0 + wm * 32 + mf * 16 + gid;
        int tok0 = g_slot_tok[e * CAP + r0];
        int tok1 = g_slot_tok[e * CAP + r0 + 8];
        float p0 = (tok0 >= 0) ? g_prob[tok0] : 0.f;
        float p1 = (tok1 >= 0) ? g_prob[tok1] : 0.f;
        #pragma unroll
        for (int j = 0; j < 8; j++) {
            int col = n0 + wn * 64 + j * 8 + tig * 2;
            if (tok0 >= 0) {
                float2 v = make_float2(p0 * c[mf][j][0], p0 * c[mf][j][1]);
                *(float2*)(out + (size_t)tok0 * H_DIM + col) = v;
            }
            if (tok1 >= 0) {
                float2 v = make_float2(p1 * c[mf][j][2], p1 * c[mf][j][3]);
                *(float2*)(out + (size_t)tok1 * H_DIM + col) = v;
            }
        }
    }
}

// ============================================================================
extern "C" void kernel_launch(void* const* d_in, const int* in_sizes, int n_in,
                              void* d_out, int out_size) {
    const float* x  = (const float*)d_in[0];
    const float* gw = (const float*)d_in[1];
    const float* w1 = (const float*)d_in[2];
    const float* w2 = (const float*)d_in[3];
    float* out = (float*)d_out;

    cudaFuncSetAttribute(gemm1_mma, cudaFuncAttributeMaxDynamicSharedMemorySize, SMEM_BYTES);
    cudaFuncSetAttribute(gemm2_mma, cudaFuncAttributeMaxDynamicSharedMemorySize, SMEM_BYTES);

    gate_kernel<<<T_TOK / 16, 256>>>(x, gw);
    scan_kernel<<<1, 256>>>();
    cudaMemsetAsync(d_out, 0, (size_t)out_size * sizeof(float));
    gemm1_mma<<<dim3(CAP / 128, I_DIM / 128, E_NUM), 256, SMEM_BYTES>>>(x, w1);
    gemm2_mma<<<dim3(CAP / 128, H_DIM / 128, E_NUM), 256, SMEM_BYTES>>>(w2, out);
}

// round 15
// speedup vs baseline: 3.2412x; 1.0245x over previous
#include <cuda_runtime.h>
#include <math.h>
#include <stdint.h>

#define T_TOK 8192
#define H_DIM 2048
#define I_DIM 2048
#define E_NUM 8
#define CAP   1280

#define NCHUNK 64              // K=2048 / 32
#define AST 36                 // A smem row stride (floats)
#define BST 136                // B smem row stride (floats)
#define A_ELEMS (128 * AST)    // 4608
#define B_ELEMS (32 * BST)     // 4352
#define STAGE_ELEMS (A_ELEMS + B_ELEMS)
#define SMEM_BYTES (2 * STAGE_ELEMS * 4)

// ---- scratch (static __device__ — no allocations) ----
__device__ int   g_top1[T_TOK];
__device__ float g_prob[T_TOK];
__device__ int   g_slot_tok[E_NUM * CAP];
__device__ float g_mid[(size_t)E_NUM * CAP * I_DIM];
__device__ float g_x32[(size_t)T_TOK * H_DIM];                // tf32-rounded x
__device__ float g_w132[(size_t)E_NUM * H_DIM * I_DIM];      // tf32-rounded w1
__device__ float g_w232[(size_t)E_NUM * I_DIM * H_DIM];      // tf32-rounded w2

// ---------------------------------------------------------------- helpers ---
__device__ __forceinline__ uint32_t smem_u32(const void* p) {
    uint32_t a;
    asm("{ .reg .u64 t; cvta.to.shared.u64 t, %1; cvt.u32.u64 %0, t; }" : "=r"(a) : "l"(p));
    return a;
}
__device__ __forceinline__ uint32_t f2tf32(float f) {
    uint32_t u;
    asm("cvt.rna.tf32.f32 %0, %1;" : "=r"(u) : "f"(f));
    return u;
}
__device__ __forceinline__ float gelu_exact(float v) {
    return 0.5f * v * (1.0f + erff(v * 0.70710678118654752440f));
}
__device__ __forceinline__ void mma_tf32(float* c, const uint32_t* a, uint32_t b0, uint32_t b1) {
    asm volatile(
        "mma.sync.aligned.m16n8k8.row.col.f32.tf32.tf32.f32 "
        "{%0,%1,%2,%3}, {%4,%5,%6,%7}, {%8,%9}, {%0,%1,%2,%3};"
        : "+f"(c[0]), "+f"(c[1]), "+f"(c[2]), "+f"(c[3])
        : "r"(a[0]), "r"(a[1]), "r"(a[2]), "r"(a[3]), "r"(b0), "r"(b1));
}
#define CP16(dst, src, sz) \
    asm volatile("cp.async.cg.shared.global [%0], [%1], 16, %2;" \
                 :: "r"(dst), "l"(src), "r"(sz) : "memory")
#define CP_COMMIT() asm volatile("cp.async.commit_group;" ::: "memory")
#define CP_WAIT0()  asm volatile("cp.async.wait_group 0;" ::: "memory")

// ============================================================================
// 0) tf32 pre-round: dst = round_rna_tf32(src), elementwise float4
// ============================================================================
__global__ void tf32_round_kernel(const float4* __restrict__ src, float4* __restrict__ dst, int n4) {
    int i = blockIdx.x * blockDim.x + threadIdx.x;
    int stride = gridDim.x * blockDim.x;
    for (; i < n4; i += stride) {
        float4 v = src[i];
        float4 o;
        o.x = __uint_as_float(f2tf32(v.x));
        o.y = __uint_as_float(f2tf32(v.y));
        o.z = __uint_as_float(f2tf32(v.z));
        o.w = __uint_as_float(f2tf32(v.w));
        dst[i] = o;
    }
}

// ============================================================================
// 1) Gate (reads original fp32 x — full precision logits)
// ============================================================================
__global__ void gate_kernel(const float* __restrict__ x, const float* __restrict__ gw) {
    __shared__ float st[H_DIM];
    __shared__ float slog[E_NUM];
    int tid = threadIdx.x;
    int warp = tid >> 5, lane = tid & 31;
    int t0 = blockIdx.x * 16;
    for (int tk = 0; tk < 16; tk++) {
        int t = t0 + tk;
        const float4* src = (const float4*)(x + (size_t)t * H_DIM);
        float4* dst = (float4*)st;
        for (int i = tid; i < H_DIM / 4; i += 256) dst[i] = src[i];
        __syncthreads();
        float s = 0.f;
        const float* g = gw + (size_t)warp * H_DIM;
        for (int i = lane; i < H_DIM; i += 32) s += st[i] * g[i];
        #pragma unroll
        for (int o = 16; o; o >>= 1) s += __shfl_xor_sync(0xffffffffu, s, o);
        if (lane == 0) slog[warp] = s;
        __syncthreads();
        if (tid == 0) {
            float mx = slog[0]; int am = 0;
            #pragma unroll
            for (int e = 1; e < E_NUM; e++) if (slog[e] > mx) { mx = slog[e]; am = e; }
            float den = 0.f;
            #pragma unroll
            for (int e = 0; e < E_NUM; e++) den += expf(slog[e] - mx);
            g_top1[t] = am;
            g_prob[t] = 1.0f / den;
        }
        __syncthreads();
    }
}

// ============================================================================
// 2) Routing scan
// ============================================================================
__global__ void scan_kernel() {
    __shared__ int sc[2][256][E_NUM];
    int tid = threadIdx.x;
    for (int i = tid; i < E_NUM * CAP; i += 256) g_slot_tok[i] = -1;
    int h[E_NUM];
    #pragma unroll
    for (int e = 0; e < E_NUM; e++) h[e] = 0;
    int base = tid * 32;
    for (int j = 0; j < 32; j++) h[g_top1[base + j]]++;
    #pragma unroll
    for (int e = 0; e < E_NUM; e++) sc[0][tid][e] = h[e];
    __syncthreads();
    int src = 0;
    for (int d = 1; d < 256; d <<= 1) {
        #pragma unroll
        for (int e = 0; e < E_NUM; e++) {
            int v = sc[src][tid][e];
            if (tid >= d) v += sc[src][tid - d][e];
            sc[1 - src][tid][e] = v;
        }
        __syncthreads();
        src ^= 1;
    }
    int run[E_NUM];
    #pragma unroll
    for (int e = 0; e < E_NUM; e++) run[e] = sc[src][tid][e] - h[e];
    for (int j = 0; j < 32; j++) {
        int t = base + j;
        int e = g_top1[t];
        int r = run[e]++;
        if (r < CAP) g_slot_tok[e * CAP + r] = t;
    }
}

// ============================================================================
// 3) GEMM1 (mma.sync tf32): mid = tf32round( gelu( gather(x32) @ w132[e] ) )
//    Operands pre-rounded -> no cvt in the mainloop.
// ============================================================================
__global__ __launch_bounds__(256, 2) void gemm1_mma() {
    int e = blockIdx.z, m0 = blockIdx.x * 128, n0 = blockIdx.y * 128;
    if (g_slot_tok[e * CAP + m0] < 0) return;
    extern __shared__ float smem[];
    uint32_t sb = smem_u32(smem);
    int tid = threadIdx.x, lane = tid & 31, wid = tid >> 5;
    int gid = lane >> 2, tig = lane & 3;
    int wm = wid & 3, wn = wid >> 2;

    const float* agp[4]; uint32_t aso[4], asz[4];
    #pragma unroll
    for (int i = 0; i < 4; i++) {
        int idx = tid + i * 256, row = idx >> 3, seg = idx & 7;
        int tok = g_slot_tok[e * CAP + m0 + row];
        asz[i] = (tok >= 0) ? 16u : 0u;
        agp[i] = g_x32 + (size_t)(tok < 0 ? 0 : tok) * H_DIM + seg * 4;
        aso[i] = (uint32_t)(row * AST + seg * 4) * 4u;
    }
    const float* bgp[4]; uint32_t bso[4];
    const float* wbase = g_w132 + (size_t)e * H_DIM * I_DIM;
    #pragma unroll
    for (int i = 0; i < 4; i++) {
        int idx = tid + i * 256, brow = idx >> 5, bseg = idx & 31;
        bgp[i] = wbase + (size_t)brow * I_DIM + n0 + bseg * 4;
        bso[i] = (uint32_t)(A_ELEMS + brow * BST + bseg * 4) * 4u;
    }

    float c[2][8][4];
    #pragma unroll
    for (int mf = 0; mf < 2; mf++)
        #pragma unroll
        for (int j = 0; j < 8; j++)
            #pragma unroll
            for (int q = 0; q < 4; q++) c[mf][j][q] = 0.f;

    {
        uint32_t base = sb;
        #pragma unroll
        for (int i = 0; i < 4; i++) CP16(base + aso[i], agp[i], asz[i]);
        #pragma unroll
        for (int i = 0; i < 4; i++) CP16(base + bso[i], bgp[i], 16u);
        CP_COMMIT();
    }

    for (int kc = 0; kc < NCHUNK; kc++) {
        int buf = kc & 1;
        CP_WAIT0();
        __syncthreads();
        if (kc + 1 < NCHUNK) {
            uint32_t base = sb + (uint32_t)((buf ^ 1) * STAGE_ELEMS * 4);
            int kt = (kc + 1) * 32;
            #pragma unroll
            for (int i = 0; i < 4; i++) CP16(base + aso[i], agp[i] + kt, asz[i]);
            #pragma unroll
            for (int i = 0; i < 4; i++) CP16(base + bso[i], bgp[i] + (size_t)kt * I_DIM, 16u);
            CP_COMMIT();
        }
        const uint32_t* As = (const uint32_t*)(smem + buf * STAGE_ELEMS);
        const uint32_t* Bs = As + A_ELEMS;
        #pragma unroll
        for (int k8 = 0; k8 < 4; k8++) {
            int kk = k8 * 8;
            uint32_t a[2][4];
            #pragma unroll
            for (int mf = 0; mf < 2; mf++) {
                int r0 = wm * 32 + mf * 16 + gid;
                a[mf][0] = As[r0 * AST + kk + tig];
                a[mf][1] = As[(r0 + 8) * AST + kk + tig];
                a[mf][2] = As[r0 * AST + kk + tig + 4];
                a[mf][3] = As[(r0 + 8) * AST + kk + tig + 4];
            }
            #pragma unroll
            for (int j = 0; j < 8; j++) {
                int nn = wn * 64 + j * 8 + gid;
                uint32_t b0 = Bs[(kk + tig) * BST + nn];
                uint32_t b1 = Bs[(kk + tig + 4) * BST + nn];
                mma_tf32(c[0][j], a[0], b0, b1);
                mma_tf32(c[1][j], a[1], b0, b1);
            }
        }
        __syncthreads();
    }

    // epilogue: gelu, then tf32-round so GEMM2's A side needs no cvt
    #pragma unroll
    for (int mf = 0; mf < 2; mf++) {
        int row = m0 + wm * 32 + mf * 16 + gid;
        #pragma unroll
        for (int j = 0; j < 8; j++) {
            int col = n0 + wn * 64 + j * 8 + tig * 2;
            float* p0 = g_mid + ((size_t)e * CAP + row) * I_DIM + col;
            float2 v0, v1;
            v0.x = __uint_as_float(f2tf32(gelu_exact(c[mf][j][0])));
            v0.y = __uint_as_float(f2tf32(gelu_exact(c[mf][j][1])));
            v1.x = __uint_as_float(f2tf32(gelu_exact(c[mf][j][2])));
            v1.y = __uint_as_float(f2tf32(gelu_exact(c[mf][j][3])));
            *(float2*)p0 = v0;
            *(float2*)(p0 + (size_t)8 * I_DIM) = v1;
        }
    }
}

// ============================================================================
// 4) GEMM2 (mma.sync tf32): out[tok] = prob[tok] * ( mid @ w232[e] ), scatter
// ============================================================================
__global__ __launch_bounds__(256, 2) void gemm2_mma(float* __restrict__ out) {
    int e = blockIdx.z, m0 = blockIdx.x * 128, n0 = blockIdx.y * 128;
    if (g_slot_tok[e * CAP + m0] < 0) return;
    extern __shared__ float smem[];
    uint32_t sb = smem_u32(smem);
    int tid = threadIdx.x, lane = tid & 31, wid = tid >> 5;
    int gid = lane >> 2, tig = lane & 3;
    int wm = wid & 3, wn = wid >> 2;

    const float* agp[4]; uint32_t aso[4];
    #pragma unroll
    for (int i = 0; i < 4; i++) {
        int idx = tid + i * 256, row = idx >> 3, seg = idx & 7;
        agp[i] = g_mid + ((size_t)e * CAP + m0 + row) * I_DIM + seg * 4;
        aso[i] = (uint32_t)(row * AST + seg * 4) * 4u;
    }
    const float* bgp[4]; uint32_t bso[4];
    const float* wbase = g_w232 + (size_t)e * I_DIM * H_DIM;
    #pragma unroll
    for (int i = 0; i < 4; i++) {
        int idx = tid + i * 256, brow = idx >> 5, bseg = idx & 31;
        bgp[i] = wbase + (size_t)brow * H_DIM + n0 + bseg * 4;
        bso[i] = (uint32_t)(A_ELEMS + brow * BST + bseg * 4) * 4u;
    }

    float c[2][8][4];
    #pragma unroll
    for (int mf = 0; mf < 2; mf++)
        #pragma unroll
        for (int j = 0; j < 8; j++)
            #pragma unroll
            for (int q = 0; q < 4; q++) c[mf][j][q] = 0.f;

    {
        uint32_t base = sb;
        #pragma unroll
        for (int i = 0; i < 4; i++) CP16(base + aso[i], agp[i], 16u);
        #pragma unroll
        for (int i = 0; i < 4; i++) CP16(base + bso[i], bgp[i], 16u);
        CP_COMMIT();
    }

    for (int kc = 0; kc < NCHUNK; kc++) {
        int buf = kc & 1;
        CP_WAIT0();
        __syncthreads();
        if (kc + 1 < NCHUNK) {
            uint32_t base = sb + (uint32_t)((buf ^ 1) * STAGE_ELEMS * 4);
            int kt = (kc + 1) * 32;
            #pragma unroll
            for (int i = 0; i < 4; i++) CP16(base + aso[i], agp[i] + kt, 16u);
            #pragma unroll
            for (int i = 0; i < 4; i++) CP16(base + bso[i], bgp[i] + (size_t)kt * H_DIM, 16u);
            CP_COMMIT();
        }
        const uint32_t* As = (const uint32_t*)(smem + buf * STAGE_ELEMS);
        const uint32_t* Bs = As + A_ELEMS;
        #pragma unroll
        for (int k8 = 0; k8 < 4; k8++) {
            int kk = k8 * 8;
            uint32_t a[2][4];
            #pragma unroll
            for (int mf = 0; mf < 2; mf++) {
                int r0 = wm * 32 + mf * 16 + gid;
                a[mf][0] = As[r0 * AST + kk + tig];
                a[mf][1] = As[(r0 + 8) * AST + kk + tig];
                a[mf][2] = As[r0 * AST + kk + tig + 4];
                a[mf][3] = As[(r0 + 8) * AST + kk + tig + 4];
            }
            #pragma unroll
            for (int j = 0; j < 8; j++) {
                int nn = wn * 64 + j * 8 + gid;
                uint32_t b0 = Bs[(kk + tig) * BST + nn];
                uint32_t b1 = Bs[(kk + tig + 4) * BST + nn];
                mma_tf32(c[0][j], a[0], b0, b1);
                mma_tf32(c[1][j], a[1], b0, b1);
            }
        }
        __syncthreads();
    }

    // epilogue: scale by prob, scatter to out (skip dropped slots)
    #pragma unroll
    for (int mf = 0; mf < 2; mf++) {
        int r0 = m0 + wm * 32 + mf * 16 + gid;
        int tok0 = g_slot_tok[e * CAP + r0];
        int tok1 = g_slot_tok[e * CAP + r0 + 8];
        float p0 = (tok0 >= 0) ? g_prob[tok0] : 0.f;
        float p1 = (tok1 >= 0) ? g_prob[tok1] : 0.f;
        #pragma unroll
        for (int j = 0; j < 8; j++) {
            int col = n0 + wn * 64 + j * 8 + tig * 2;
            if (tok0 >= 0) {
                float2 v = make_float2(p0 * c[mf][j][0], p0 * c[mf][j][1]);
                *(float2*)(out + (size_t)tok0 * H_DIM + col) = v;
            }
            if (tok1 >= 0) {
                float2 v = make_float2(p1 * c[mf][j][2], p1 * c[mf][j][3]);
                *(float2*)(out + (size_t)tok1 * H_DIM + col) = v;
            }
        }
    }
}

// ============================================================================
extern "C" void kernel_launch(void* const* d_in, const int* in_sizes, int n_in,
                              void* d_out, int out_size) {
    const float* x  = (const float*)d_in[0];
    const float* gw = (const float*)d_in[1];
    const float* w1 = (const float*)d_in[2];
    const float* w2 = (const float*)d_in[3];
    float* out = (float*)d_out;

    cudaFuncSetAttribute(gemm1_mma, cudaFuncAttributeMaxDynamicSharedMemorySize, SMEM_BYTES);
    cudaFuncSetAttribute(gemm2_mma, cudaFuncAttributeMaxDynamicSharedMemorySize, SMEM_BYTES);

    float* x32;  cudaGetSymbolAddress((void**)&x32,  g_x32);
    float* w132; cudaGetSymbolAddress((void**)&w132, g_w132);
    float* w232; cudaGetSymbolAddress((void**)&w232, g_w232);

    const int CONV_GRID = 1184, CONV_BLK = 256;
    tf32_round_kernel<<<CONV_GRID, CONV_BLK>>>((const float4*)x,  (float4*)x32,  T_TOK * H_DIM / 4);
    tf32_round_kernel<<<CONV_GRID, CONV_BLK>>>((const float4*)w1, (float4*)w132, E_NUM * H_DIM * I_DIM / 4);
    tf32_round_kernel<<<CONV_GRID, CONV_BLK>>>((const float4*)w2, (float4*)w232, E_NUM * I_DIM * H_DIM / 4);

    gate_kernel<<<T_TOK / 16, 256>>>(x, gw);
    scan_kernel<<<1, 256>>>();
    cudaMemsetAsync(d_out, 0, (size_t)out_size * sizeof(float));
    gemm1_mma<<<dim3(CAP / 128, I_DIM / 128, E_NUM), 256, SMEM_BYTES>>>();
    gemm2_mma<<<dim3(CAP / 128, H_DIM / 128, E_NUM), 256, SMEM_BYTES>>>(out);
}